// round 6
// baseline (speedup 1.0000x reference)
#include <cuda_runtime.h>
#include <cuda_bf16.h>
#include <cuda_fp16.h>
#include <math.h>
#include <stdint.h>

// Problem constants
#define Tn 512
#define Bn 8
#define En 1024
#define Hn 1024
#define Dn 512
#define Vn 32000
#define MROWS (Tn * Bn)   // 4096

// ---------------- scratch (device globals; no allocations allowed) ----------
__device__ float g_X[MROWS * En];
__device__ float g_R0pre[MROWS * Dn];
__device__ float g_R1pre[MROWS * Dn];
__device__ float g_R0[MROWS * Dn];
__device__ float g_R1[MROWS * Dn];
__device__ float g_Hpre[MROWS * Hn];
__device__ float g_H[MROWS * Hn];
__device__ unsigned g_flags[128 * 32];   // per-CTA arrival flags, 128B stride
__device__ unsigned g_token[4 * 32];     // published step tokens, 128B stride
__device__ unsigned g_done[4];           // reset counters

// fp16 operands for the tensor-core logits GEMM
__device__ __half g_Wh[(size_t)Vn * Hn];
__device__ __half g_Hh[(size_t)MROWS * Hn];

// ================= portable PTX helpers (sm_80+) ============================
__device__ __forceinline__ uint32_t smem_u32(const void* p) {
    uint32_t a;
    asm("{ .reg .u64 t; cvta.to.shared.u64 t, %1; cvt.u32.u64 %0, t; }" : "=r"(a) : "l"(p));
    return a;
}
__device__ __forceinline__ void cp_async16(uint32_t saddr, const void* gaddr) {
    asm volatile("cp.async.cg.shared.global [%0], [%1], 16;" :: "r"(saddr), "l"(gaddr));
}
#define CP_COMMIT() asm volatile("cp.async.commit_group;" ::: "memory")
#define CP_WAIT(N)  asm volatile("cp.async.wait_group %0;" :: "n"(N) : "memory")

__device__ __forceinline__ void ldsm_x4(uint32_t& r0, uint32_t& r1, uint32_t& r2,
                                        uint32_t& r3, uint32_t addr) {
    asm volatile("ldmatrix.sync.aligned.m8n8.x4.shared.b16 {%0,%1,%2,%3}, [%4];"
                 : "=r"(r0), "=r"(r1), "=r"(r2), "=r"(r3) : "r"(addr));
}
__device__ __forceinline__ void mma16816h(float* c, const uint32_t* a, const uint32_t* b) {
    asm volatile(
        "mma.sync.aligned.m16n8k16.row.col.f32.f16.f16.f32 "
        "{%0,%1,%2,%3}, {%4,%5,%6,%7}, {%8,%9}, {%0,%1,%2,%3};"
        : "+f"(c[0]), "+f"(c[1]), "+f"(c[2]), "+f"(c[3])
        : "r"(a[0]), "r"(a[1]), "r"(a[2]), "r"(a[3]), "r"(b[0]), "r"(b[1]));
}

// ---------------- embedding gather ------------------------------------------
__global__ void embed_kernel(const int* __restrict__ ids,
                             const float* __restrict__ emb)
{
    int m = blockIdx.x;
    int id = __ldg(ids + m);
    float4 v = __ldg(((const float4*)(emb + (size_t)id * En)) + threadIdx.x);
    ((float4*)(g_X + (size_t)m * En))[threadIdx.x] = v;
}

// ---------------- fp32 -> fp16 conversion ------------------------------------
__global__ void cvt_h_kernel(const float* __restrict__ src,
                             __half* __restrict__ dst, int n4)
{
    int i = blockIdx.x * blockDim.x + threadIdx.x;
    if (i >= n4) return;
    float4 v = ((const float4*)src)[i];
    __half2* dp = (__half2*)dst;
    dp[i * 2 + 0] = __floats2half2_rn(v.x, v.y);
    dp[i * 2 + 1] = __floats2half2_rn(v.z, v.w);
}

// ---------------- logits GEMM on mma.sync (single-pass fp16) -----------------
// CTA tile 128x256, K-chunk 64, 3-stage cp.async pipeline, SW128 swizzle.
// 8 warps as 2(m) x 4(n); warp tile 64x64.
#define KCH 64
#define ATILE (128 * KCH * 2)      // 16384
#define BTILE (256 * KCH * 2)      // 32768
#define STG (ATILE + BTILE)        // 49152
#define NSTAGE 3

__global__ void __launch_bounds__(256, 1)
logits_mma(const __half* __restrict__ A, const __half* __restrict__ B,
           const float* __restrict__ bias, float* __restrict__ C)
{
    extern __shared__ __align__(16) char sm[];
    uint32_t sbase = smem_u32(sm);

    int tid = threadIdx.x, lane = tid & 31, wid = tid >> 5;
    int wm = wid >> 2, wn = wid & 3;              // 2 x 4 warp grid
    int m0 = blockIdx.x * 128, n0 = blockIdx.y * 256;

    const __half* gA = A + (size_t)m0 * En;
    const __half* gB = B + (size_t)n0 * En;

    float acc[4][8][4];
#pragma unroll
    for (int a = 0; a < 4; a++)
#pragma unroll
        for (int b = 0; b < 8; b++)
#pragma unroll
            for (int cx = 0; cx < 4; cx++) acc[a][b][cx] = 0.f;

    auto issue_stage = [&](int s, int kc) {
        uint32_t stb = sbase + s * STG;
        const __half* ga = gA + kc * KCH;
#pragma unroll
        for (int i = 0; i < 4; ++i) {            // A: 128 rows x 8 16B-chunks
            int q = tid + i * 256;
            int r = q >> 3, c = q & 7;
            uint32_t sa = stb + ((r >> 3) << 10) + ((r & 7) << 7) + ((c ^ (r & 7)) << 4);
            cp_async16(sa, ga + (size_t)r * En + c * 8);
        }
        const __half* gb = gB + kc * KCH;
        uint32_t tb = stb + ATILE;
#pragma unroll
        for (int i = 0; i < 8; ++i) {            // B: 256 rows x 8 16B-chunks
            int q = tid + i * 256;
            int r = q >> 3, c = q & 7;
            uint32_t sa = tb + ((r >> 3) << 10) + ((r & 7) << 7) + ((c ^ (r & 7)) << 4);
            cp_async16(sa, gb + (size_t)r * En + c * 8);
        }
    };

    issue_stage(0, 0); CP_COMMIT();
    issue_stage(1, 1); CP_COMMIT();

    const int NKC = En / KCH;   // 16
    for (int kc = 0; kc < NKC; ++kc) {
        if (kc + 2 < NKC) { issue_stage((kc + 2) % NSTAGE, kc + 2); CP_COMMIT(); CP_WAIT(2); }
        else if (kc + 1 < NKC) { CP_WAIT(1); }
        else { CP_WAIT(0); }
        __syncthreads();

        uint32_t sA = sbase + (kc % NSTAGE) * STG;
        uint32_t sB = sA + ATILE;

#pragma unroll
        for (int ks = 0; ks < KCH / 16; ++ks) {
            uint32_t ah[4][4], bh[8][2];

            int ra = (lane & 7) + ((lane >> 3) & 1) * 8;
            int ca = ks * 2 + ((lane >> 4) & 1);
#pragma unroll
            for (int mt = 0; mt < 4; ++mt) {
                int row = wm * 64 + mt * 16 + ra;
                uint32_t off = ((row >> 3) << 10) + ((row & 7) << 7)
                             + (((ca ^ (row & 7)) & 7) << 4);
                ldsm_x4(ah[mt][0], ah[mt][1], ah[mt][2], ah[mt][3], sA + off);
            }
            int rb = (lane & 7) + ((lane >> 4) & 1) * 8;
            int cb = ks * 2 + ((lane >> 3) & 1);
#pragma unroll
            for (int np = 0; np < 4; ++np) {
                int row = wn * 64 + np * 16 + rb;
                uint32_t off = ((row >> 3) << 10) + ((row & 7) << 7)
                             + (((cb ^ (row & 7)) & 7) << 4);
                ldsm_x4(bh[np * 2][0], bh[np * 2][1],
                        bh[np * 2 + 1][0], bh[np * 2 + 1][1], sB + off);
            }

#pragma unroll
            for (int mt = 0; mt < 4; ++mt)
#pragma unroll
                for (int nt = 0; nt < 8; ++nt)
                    mma16816h(acc[mt][nt], ah[mt], bh[nt]);
        }
        __syncthreads();
    }

    // epilogue: add bias, store fp32
#pragma unroll
    for (int mt = 0; mt < 4; ++mt) {
        int r0 = m0 + wm * 64 + mt * 16 + (lane >> 2);
#pragma unroll
        for (int nt = 0; nt < 8; ++nt) {
            int cc = n0 + wn * 64 + nt * 8 + (lane & 3) * 2;
            float2 bia = *(const float2*)(bias + cc);
            float2 v0 = make_float2(acc[mt][nt][0] + bia.x, acc[mt][nt][1] + bia.y);
            float2 v1 = make_float2(acc[mt][nt][2] + bia.x, acc[mt][nt][3] + bia.y);
            *(float2*)(C + (size_t)r0 * Vn + cc) = v0;
            *(float2*)(C + (size_t)(r0 + 8) * Vn + cc) = v1;
        }
    }
}

// ---------------- generic NT SGEMM (fp32, small GEMMs) -----------------------
// blockIdx.z selects (A,W,C) pair when A1 != nullptr (dual-projection mode).
__global__ void __launch_bounds__(256, 2)
sgemm_nt(const float* __restrict__ A, const float* __restrict__ W,
         const float* __restrict__ bias, float* __restrict__ C,
         const float* __restrict__ W1, float* __restrict__ C1,
         int M, int N, int K, int flags)
{
    __shared__ __align__(16) float As[16][128];
    __shared__ __align__(16) float Ws[16][128];

    if (blockIdx.z) { W = W1; C = C1; }

    int bm0 = blockIdx.x * 128;
    int bn0 = blockIdx.y * 128;
    int tid = threadIdx.x;
    int tx = tid & 15, ty = tid >> 4;

    const float* Aptr = A + (size_t)bm0 * K;
    const float* Wptr = W + (size_t)bn0 * K;

    int q0 = tid, q1 = tid + 256;
    int r0 = q0 >> 2, kq0 = (q0 & 3) << 2;
    int r1 = q1 >> 2, kq1 = (q1 & 3) << 2;

    float4 ra0 = *(const float4*)(Aptr + (size_t)r0 * K + kq0);
    float4 ra1 = *(const float4*)(Aptr + (size_t)r1 * K + kq1);
    float4 rw0 = *(const float4*)(Wptr + (size_t)r0 * K + kq0);
    float4 rw1 = *(const float4*)(Wptr + (size_t)r1 * K + kq1);

    float acc[8][8];
#pragma unroll
    for (int i = 0; i < 8; i++)
#pragma unroll
        for (int j = 0; j < 8; j++) acc[i][j] = 0.f;

    for (int k0 = 0; k0 < K; k0 += 16) {
        As[kq0 + 0][r0] = ra0.x; As[kq0 + 1][r0] = ra0.y;
        As[kq0 + 2][r0] = ra0.z; As[kq0 + 3][r0] = ra0.w;
        As[kq1 + 0][r1] = ra1.x; As[kq1 + 1][r1] = ra1.y;
        As[kq1 + 2][r1] = ra1.z; As[kq1 + 3][r1] = ra1.w;
        Ws[kq0 + 0][r0] = rw0.x; Ws[kq0 + 1][r0] = rw0.y;
        Ws[kq0 + 2][r0] = rw0.z; Ws[kq0 + 3][r0] = rw0.w;
        Ws[kq1 + 0][r1] = rw1.x; Ws[kq1 + 1][r1] = rw1.y;
        Ws[kq1 + 2][r1] = rw1.z; Ws[kq1 + 3][r1] = rw1.w;
        __syncthreads();

        if (k0 + 16 < K) {
            const float* An = Aptr + k0 + 16;
            const float* Wn = Wptr + k0 + 16;
            ra0 = *(const float4*)(An + (size_t)r0 * K + kq0);
            ra1 = *(const float4*)(An + (size_t)r1 * K + kq1);
            rw0 = *(const float4*)(Wn + (size_t)r0 * K + kq0);
            rw1 = *(const float4*)(Wn + (size_t)r1 * K + kq1);
        }

#pragma unroll
        for (int kk = 0; kk < 16; kk++) {
            float a[8], b[8];
            *(float4*)&a[0] = *(const float4*)&As[kk][ty * 8];
            *(float4*)&a[4] = *(const float4*)&As[kk][ty * 8 + 4];
            *(float4*)&b[0] = *(const float4*)&Ws[kk][tx * 8];
            *(float4*)&b[4] = *(const float4*)&Ws[kk][tx * 8 + 4];
#pragma unroll
            for (int i = 0; i < 8; i++)
#pragma unroll
                for (int j = 0; j < 8; j++) acc[i][j] += a[i] * b[j];
        }
        __syncthreads();
    }

#pragma unroll
    for (int i = 0; i < 8; i++) {
        int m = bm0 + ty * 8 + i;
        float* crow = C + (size_t)m * N + bn0 + tx * 8;
#pragma unroll
        for (int jj = 0; jj < 8; jj += 4) {
            float4 v = make_float4(acc[i][jj], acc[i][jj + 1], acc[i][jj + 2], acc[i][jj + 3]);
            if (flags & 1) {
                int n = bn0 + tx * 8 + jj;
                v.x += __ldg(bias + n + 0); v.y += __ldg(bias + n + 1);
                v.z += __ldg(bias + n + 2); v.w += __ldg(bias + n + 3);
            }
            if (flags & 2) {
                float4 o = *(const float4*)(crow + jj);
                v.x += o.x; v.y += o.y; v.z += o.z; v.w += o.w;
            }
            *(float4*)(crow + jj) = v;
        }
    }
}

// ---------------- flag/publish grid barrier ----------------------------------
// Caller: state stores -> __syncthreads() -> scan_barrier(). Thread-0 fence is
// cumulative (bar.sync hb-edge), so state is GPU-visible before flag set.
// Aggregator observes all flags (state therefore visible), fences, publishes
// token; readers poll the single token line (L2 broadcast).
__device__ __forceinline__ void scan_barrier(unsigned* flags, unsigned* token,
                                             int bidg, int ngroup, bool isagg,
                                             unsigned tgt, int tid)
{
    if (tid == 0) { __threadfence(); *(volatile unsigned*)(flags + bidg * 32) = tgt; }
    if (isagg) {
        if (tid < ngroup) {
            volatile unsigned* f = flags + tid * 32;
            while (*f < tgt) {}
        }
        __syncthreads();
        if (tid == 0) { __threadfence(); *(volatile unsigned*)token = tgt; }
    }
    if (tid == 0) {
        while (*(volatile unsigned*)token < tgt) {}
        __threadfence();
    }
    __syncthreads();
}

__device__ __forceinline__ void scan_reset(unsigned* flags, int ngroup,
                                           unsigned* token, unsigned* done,
                                           unsigned nctas, int tid)
{
    if (tid == 0) {
        unsigned v = atomicAdd(done, 1u);
        if (v == nctas - 1u) {
            *done = 0u;
            *token = 0u;
            for (int i = 0; i < ngroup; ++i) flags[i * 32] = 0u;
            __threadfence();
        }
    }
}

// ---------------- reservoir scans (both reservoirs, 64 CTAs each) -----------
__global__ void __launch_bounds__(256)
rscan_kernel(const float* __restrict__ pre0, const float* __restrict__ pre1,
             const float* __restrict__ W0, const float* __restrict__ W1,
             float* __restrict__ R0, float* __restrict__ R1)
{
    __shared__ __align__(16) float sW[8 * Dn];
    __shared__ __align__(16) float sR[Bn * Dn];

    int res  = blockIdx.x >> 6;
    int bidg = blockIdx.x & 63;
    int j0   = bidg * 8;
    const float* pre  = res ? pre1 : pre0;
    const float* Wres = res ? W1 : W0;
    float* Rout = res ? R1 : R0;
    unsigned* flags = g_flags + res * 64 * 32;
    unsigned* token = g_token + res * 32;

    int tid = threadIdx.x, lane = tid & 31, b = tid >> 5;

    for (int i = tid; i < 8 * Dn / 4; i += 256)
        ((float4*)sW)[i] = ((const float4*)(Wres + (size_t)j0 * Dn))[i];
    __syncthreads();

    for (int t = 0; t < Tn; ++t) {
        if (t == 0) {
            float4 z = make_float4(0.f, 0.f, 0.f, 0.f);
            for (int i = tid; i < Bn * Dn / 4; i += 256) ((float4*)sR)[i] = z;
        } else {
            for (int i = tid; i < Bn * Dn / 4; i += 256) {
                int bb = i >> 7, c = i & 127;
                ((float4*)sR)[i] =
                    __ldcg(((const float4*)(Rout + ((size_t)bb * Tn + (t - 1)) * Dn)) + c);
            }
        }
        __syncthreads();

        const float4* rb = (const float4*)(sR + b * Dn);
        float4 rv[4];
#pragma unroll
        for (int i = 0; i < 4; i++) rv[i] = rb[i * 32 + lane];

        float myout = 0.f;
#pragma unroll
        for (int jj = 0; jj < 8; ++jj) {
            const float4* wr = (const float4*)(sW + jj * Dn);
            float sv = 0.f;
#pragma unroll
            for (int i = 0; i < 4; i++) {
                float4 w4 = wr[i * 32 + lane];
                sv += rv[i].x * w4.x + rv[i].y * w4.y + rv[i].z * w4.z + rv[i].w * w4.w;
            }
#pragma unroll
            for (int off = 16; off; off >>= 1) sv += __shfl_xor_sync(0xffffffffu, sv, off);
            if (lane == jj) myout = sv;
        }
        if (lane < 8) {
            int j = j0 + lane;
            size_t row = (size_t)b * Tn + t;
            float rold = sR[b * Dn + j];
            float p = __ldcg(pre + row * Dn + j);
            Rout[row * Dn + j] = 0.5f * rold + 0.5f * tanhf(p + myout);
        }
        __syncthreads();
        scan_barrier(flags, token, bidg, 64, bidg == 0, (unsigned)(t + 1), tid);
    }
    scan_reset(flags, 64, token, &g_done[res], 64u, tid);
}

// ---------------- hidden scan -------------------------------------------------
__global__ void __launch_bounds__(256)
hscan_kernel(const float* __restrict__ Hpre, const float* __restrict__ Wh,
             float* __restrict__ Hout)
{
    extern __shared__ __align__(16) float smem[];
    float* sW = smem;
    float* sH = smem + 8 * Hn;

    int tid = threadIdx.x, lane = tid & 31, b = tid >> 5;
    int bidg = blockIdx.x;
    int j0 = bidg * 8;
    unsigned* flags = g_flags;
    unsigned* token = g_token + 2 * 32;

    for (int i = tid; i < 8 * Hn / 4; i += 256)
        ((float4*)sW)[i] = ((const float4*)(Wh + (size_t)j0 * Hn))[i];
    __syncthreads();

    for (int t = 0; t < Tn; ++t) {
        if (t == 0) {
            float4 z = make_float4(0.f, 0.f, 0.f, 0.f);
            for (int i = tid; i < Bn * Hn / 4; i += 256) ((float4*)sH)[i] = z;
        } else {
            for (int i = tid; i < Bn * Hn / 4; i += 256) {
                int bb = i >> 8, c = i & 255;
                ((float4*)sH)[i] =
                    __ldcg(((const float4*)(Hout + ((size_t)bb * Tn + (t - 1)) * Hn)) + c);
            }
        }
        __syncthreads();

        const float4* hb = (const float4*)(sH + b * Hn);
        float4 hv[8];
#pragma unroll
        for (int i = 0; i < 8; i++) hv[i] = hb[i * 32 + lane];

        float myout = 0.f;
#pragma unroll
        for (int jj = 0; jj < 8; ++jj) {
            const float4* wr = (const float4*)(sW + jj * Hn);
            float sv = 0.f;
#pragma unroll
            for (int i = 0; i < 8; i++) {
                float4 w4 = wr[i * 32 + lane];
                sv += hv[i].x * w4.x + hv[i].y * w4.y + hv[i].z * w4.z + hv[i].w * w4.w;
            }
#pragma unroll
            for (int off = 16; off; off >>= 1) sv += __shfl_xor_sync(0xffffffffu, sv, off);
            if (lane == jj) myout = sv;
        }
        if (lane < 8) {
            int j = j0 + lane;
            size_t row = (size_t)b * Tn + t;
            float p = __ldcg(Hpre + row * Hn + j);
            Hout[row * Hn + j] = tanhf(p + myout);
        }
        __syncthreads();
        scan_barrier(flags, token, bidg, 128, bidg == 0, (unsigned)(t + 1), tid);
    }
    scan_reset(flags, 128, token, &g_done[2], 128u, tid);
}

// ---------------- launch ------------------------------------------------------
extern "C" void kernel_launch(void* const* d_in, const int* in_sizes, int n_in,
                              void* d_out, int out_size)
{
    const int*   ids   = (const int*)  d_in[0];
    const float* emb   = (const float*)d_in[1];
    const float* W_x   = (const float*)d_in[2];
    const float* W_h   = (const float*)d_in[3];
    const float* b_h   = (const float*)d_in[4];
    const float* Win0  = (const float*)d_in[5];
    const float* Wres0 = (const float*)d_in[6];
    const float* U0    = (const float*)d_in[7];
    const float* Win1  = (const float*)d_in[8];
    const float* Wres1 = (const float*)d_in[9];
    const float* U1    = (const float*)d_in[10];
    const float* outW  = (const float*)d_in[11];
    const float* outb  = (const float*)d_in[12];
    float* out = (float*)d_out;

    float *X, *R0pre, *R1pre, *R0, *R1, *Hpre, *Hst;
    __half *Wh16, *Hh16;
    cudaGetSymbolAddress((void**)&X,     g_X);
    cudaGetSymbolAddress((void**)&R0pre, g_R0pre);
    cudaGetSymbolAddress((void**)&R1pre, g_R1pre);
    cudaGetSymbolAddress((void**)&R0,    g_R0);
    cudaGetSymbolAddress((void**)&R1,    g_R1);
    cudaGetSymbolAddress((void**)&Hpre,  g_Hpre);
    cudaGetSymbolAddress((void**)&Hst,   g_H);
    cudaGetSymbolAddress((void**)&Wh16,  g_Wh);
    cudaGetSymbolAddress((void**)&Hh16,  g_Hh);

    cudaFuncSetAttribute(hscan_kernel,
                         cudaFuncAttributeMaxDynamicSharedMemorySize, 65536);
    cudaFuncSetAttribute(logits_mma,
                         cudaFuncAttributeMaxDynamicSharedMemorySize, NSTAGE * STG);

    // 1) embedding gather + out_W conversion
    embed_kernel<<<MROWS, 256>>>(ids, emb);
    cvt_h_kernel<<<(Vn * Hn / 4 + 255) / 256, 256>>>(outW, Wh16, Vn * Hn / 4);

    // 2) input projections (both reservoirs in one launch via z)
    sgemm_nt<<<dim3(MROWS / 128, Dn / 128, 2), 256>>>(X, Win0, nullptr, R0pre,
                                                      Win1, R1pre, MROWS, Dn, En, 0);
    sgemm_nt<<<dim3(MROWS / 128, Hn / 128, 1), 256>>>(X, W_x, b_h, Hpre,
                                                      nullptr, nullptr, MROWS, Hn, En, 1);

    // 3) sequential reservoir scans
    rscan_kernel<<<128, 256>>>(R0pre, R1pre, Wres0, Wres1, R0, R1);

    // 4) reservoir -> hidden projections (accumulate)
    sgemm_nt<<<dim3(MROWS / 128, Hn / 128, 1), 256>>>(R0, U0, nullptr, Hpre,
                                                      nullptr, nullptr, MROWS, Hn, Dn, 2);
    sgemm_nt<<<dim3(MROWS / 128, Hn / 128, 1), 256>>>(R1, U1, nullptr, Hpre,
                                                      nullptr, nullptr, MROWS, Hn, Dn, 2);

    // 5) sequential hidden scan
    hscan_kernel<<<128, 256, 65536>>>(Hpre, W_h, Hst);
    cvt_h_kernel<<<(MROWS * Hn / 4 + 255) / 256, 256>>>(Hst, Hh16, MROWS * Hn / 4);

    // 6) logits GEMM + bias (fp16 mma.sync, 128x256 tiles, 3-stage pipeline)
    logits_mma<<<dim3(MROWS / 128, Vn / 256), 256, NSTAGE * STG>>>(Hh16, Wh16, outb, out);
}

// round 7
// speedup vs baseline: 1.3017x; 1.3017x over previous
#include <cuda_runtime.h>
#include <cuda_fp16.h>
#include <math.h>
#include <stdint.h>

// Problem constants
#define Tn 512
#define Bn 8
#define En 1024
#define Hn 1024
#define Dn 512
#define Vn 32000
#define MROWS (Tn * Bn)   // 4096
#define KCAT 2048         // [X | R0 | R1] concat width

// ---------------- scratch (device globals; no allocations allowed) ----------
__device__ float g_R0pre[MROWS * Dn];
__device__ float g_R1pre[MROWS * Dn];
__device__ float g_R0[MROWS * Dn];
__device__ float g_R1[MROWS * Dn];
__device__ float g_Hpre[MROWS * Hn];
__device__ float g_H[MROWS * Hn];
__device__ unsigned g_cnt[4];
__device__ unsigned g_done[4];

// fp16 operands
__device__ __half g_Xcat[(size_t)MROWS * KCAT];   // [X | R0 | R1]
__device__ __half g_Wcat[(size_t)Hn * KCAT];      // [W_x | U0 | U1]
__device__ __half g_Win0h[(size_t)Dn * En];
__device__ __half g_Win1h[(size_t)Dn * En];
__device__ __half g_Wh[(size_t)Vn * Hn];
__device__ __half g_Hh[(size_t)MROWS * Hn];

// ================= portable PTX helpers (sm_80+) ============================
__device__ __forceinline__ uint32_t smem_u32(const void* p) {
    uint32_t a;
    asm("{ .reg .u64 t; cvta.to.shared.u64 t, %1; cvt.u32.u64 %0, t; }" : "=r"(a) : "l"(p));
    return a;
}
__device__ __forceinline__ void cp_async16(uint32_t saddr, const void* gaddr) {
    asm volatile("cp.async.cg.shared.global [%0], [%1], 16;" :: "r"(saddr), "l"(gaddr));
}
#define CP_COMMIT() asm volatile("cp.async.commit_group;" ::: "memory")
#define CP_WAIT(N)  asm volatile("cp.async.wait_group %0;" :: "n"(N) : "memory")

__device__ __forceinline__ void ldsm_x4(uint32_t& r0, uint32_t& r1, uint32_t& r2,
                                        uint32_t& r3, uint32_t addr) {
    asm volatile("ldmatrix.sync.aligned.m8n8.x4.shared.b16 {%0,%1,%2,%3}, [%4];"
                 : "=r"(r0), "=r"(r1), "=r"(r2), "=r"(r3) : "r"(addr));
}
__device__ __forceinline__ void mma16816h(float* c, const uint32_t* a, const uint32_t* b) {
    asm volatile(
        "mma.sync.aligned.m16n8k16.row.col.f32.f16.f16.f32 "
        "{%0,%1,%2,%3}, {%4,%5,%6,%7}, {%8,%9}, {%0,%1,%2,%3};"
        : "+f"(c[0]), "+f"(c[1]), "+f"(c[2]), "+f"(c[3])
        : "r"(a[0]), "r"(a[1]), "r"(a[2]), "r"(a[3]), "r"(b[0]), "r"(b[1]));
}

// ---------------- embedding gather -> fp16 Xcat[:, 0:1024] -------------------
__global__ void embed_h(const int* __restrict__ ids, const float* __restrict__ emb,
                        __half* __restrict__ Xcat)
{
    int m = blockIdx.x;
    int id = __ldg(ids + m);
    float4 v = __ldg(((const float4*)(emb + (size_t)id * En)) + threadIdx.x);
    __half2 h0 = __floats2half2_rn(v.x, v.y);
    __half2 h1 = __floats2half2_rn(v.z, v.w);
    __half2* dst = (__half2*)(Xcat + (size_t)m * KCAT) + threadIdx.x * 2;
    dst[0] = h0; dst[1] = h1;
}

// ---------------- fp32 -> fp16 contiguous conversion --------------------------
__global__ void cvt_h_kernel(const float* __restrict__ src,
                             __half* __restrict__ dst, int n4)
{
    int i = blockIdx.x * blockDim.x + threadIdx.x;
    if (i >= n4) return;
    float4 v = ((const float4*)src)[i];
    __half2* dp = (__half2*)dst;
    dp[i * 2 + 0] = __floats2half2_rn(v.x, v.y);
    dp[i * 2 + 1] = __floats2half2_rn(v.z, v.w);
}

// ---------------- R0,R1 -> fp16 into Xcat[:, 1024:2048] ----------------------
__global__ void cvt_r_kernel(const float* __restrict__ R0, const float* __restrict__ R1,
                             __half* __restrict__ Xcat)
{
    int i = blockIdx.x * blockDim.x + threadIdx.x;   // over MROWS*1024/4 groups
    int m = i >> 8;                                   // 256 groups of 4 per row
    int col = (i & 255) * 4;                          // 0..1020
    const float* R = (col >= Dn) ? R1 : R0;
    int d = col & (Dn - 1);
    float4 v = *(const float4*)(R + (size_t)m * Dn + d);
    __half2* p = (__half2*)(Xcat + (size_t)m * KCAT + En + col);
    p[0] = __floats2half2_rn(v.x, v.y);
    p[1] = __floats2half2_rn(v.z, v.w);
}

// ---------------- pack [W_x | U0 | U1] -> fp16 Wcat --------------------------
__global__ void pack_wcat(const float* __restrict__ Wx, const float* __restrict__ U0,
                          const float* __restrict__ U1, __half* __restrict__ Wcat)
{
    int n = blockIdx.x;            // 0..1023
    int c = threadIdx.x * 4;       // 512 threads * 4 = 2048
    const float* src;
    if (c < En)            src = Wx + (size_t)n * En + c;
    else if (c < En + Dn)  src = U0 + (size_t)n * Dn + (c - En);
    else                   src = U1 + (size_t)n * Dn + (c - En - Dn);
    float4 v = *(const float4*)src;
    __half2* p = (__half2*)(Wcat + (size_t)n * KCAT + c);
    p[0] = __floats2half2_rn(v.x, v.y);
    p[1] = __floats2half2_rn(v.z, v.w);
}

// ---------------- unified fp16 NT GEMM on mma.sync ---------------------------
// C[m][n] (+)= sum_k A[m,:]·W[n,:] (+bias[n]).  A row stride = lda, W = K.
// CTA tile 128x128, K-chunk 64, 2-stage cp.async, SW128 swizzle.
// 8 warps as 2(m) x 4(n), warp tile 64x32, 2 CTAs/SM.
#define KCH 64
#define TILEB (128 * KCH * 2)     // 16384
#define STAGEB (2 * TILEB)

__global__ void __launch_bounds__(256, 2)
gemm16(const __half* __restrict__ A, const __half* __restrict__ W,
       const float* __restrict__ bias, float* __restrict__ C,
       const __half* __restrict__ W1, float* __restrict__ C1,
       int M, int N, int K, int lda, int flags)
{
    extern __shared__ __align__(16) char sm[];
    uint32_t sbase = smem_u32(sm);

    if (blockIdx.z) { W = W1; C = C1; }

    int tid = threadIdx.x, lane = tid & 31, wid = tid >> 5;
    int wm = wid >> 2, wn = wid & 3;
    int m0 = blockIdx.x * 128, n0 = blockIdx.y * 128;

    const __half* gA = A + (size_t)m0 * lda;
    const __half* gB = W + (size_t)n0 * K;

    float acc[4][4][4];
#pragma unroll
    for (int a = 0; a < 4; a++)
#pragma unroll
        for (int b = 0; b < 4; b++)
#pragma unroll
            for (int cx = 0; cx < 4; cx++) acc[a][b][cx] = 0.f;

    auto issue_stage = [&](int s, int kc) {
        uint32_t stb = sbase + s * STAGEB;
        const __half* ga = gA + kc * KCH;
#pragma unroll
        for (int i = 0; i < 4; ++i) {
            int q = tid + i * 256;
            int r = q >> 3, c = q & 7;
            uint32_t sa = stb + ((r >> 3) << 10) + ((r & 7) << 7) + ((c ^ (r & 7)) << 4);
            cp_async16(sa, ga + (size_t)r * lda + c * 8);
        }
        const __half* gb = gB + kc * KCH;
        uint32_t tb = stb + TILEB;
#pragma unroll
        for (int i = 0; i < 4; ++i) {
            int q = tid + i * 256;
            int r = q >> 3, c = q & 7;
            uint32_t sa = tb + ((r >> 3) << 10) + ((r & 7) << 7) + ((c ^ (r & 7)) << 4);
            cp_async16(sa, gb + (size_t)r * K + c * 8);
        }
    };

    issue_stage(0, 0);
    CP_COMMIT();

    const int NKC = K / KCH;
    for (int kc = 0; kc < NKC; ++kc) {
        if (kc + 1 < NKC) {
            issue_stage((kc + 1) & 1, kc + 1);
            CP_COMMIT();
            CP_WAIT(1);
        } else {
            CP_WAIT(0);
        }
        __syncthreads();

        uint32_t sA = sbase + (kc & 1) * STAGEB;
        uint32_t sB = sA + TILEB;

#pragma unroll
        for (int ks = 0; ks < KCH / 16; ++ks) {
            uint32_t ah[4][4], bh[4][2];

            int ra = (lane & 7) + ((lane >> 3) & 1) * 8;
            int ca = ks * 2 + ((lane >> 4) & 1);
#pragma unroll
            for (int mt = 0; mt < 4; ++mt) {
                int row = wm * 64 + mt * 16 + ra;
                uint32_t off = ((row >> 3) << 10) + ((row & 7) << 7)
                             + (((ca ^ (row & 7)) & 7) << 4);
                ldsm_x4(ah[mt][0], ah[mt][1], ah[mt][2], ah[mt][3], sA + off);
            }
            int rb = (lane & 7) + ((lane >> 4) & 1) * 8;
            int cb = ks * 2 + ((lane >> 3) & 1);
#pragma unroll
            for (int np = 0; np < 2; ++np) {
                int row = wn * 32 + np * 16 + rb;
                uint32_t off = ((row >> 3) << 10) + ((row & 7) << 7)
                             + (((cb ^ (row & 7)) & 7) << 4);
                ldsm_x4(bh[np * 2][0], bh[np * 2][1],
                        bh[np * 2 + 1][0], bh[np * 2 + 1][1], sB + off);
            }

#pragma unroll
            for (int mt = 0; mt < 4; ++mt)
#pragma unroll
                for (int nt = 0; nt < 4; ++nt)
                    mma16816h(acc[mt][nt], ah[mt], bh[nt]);
        }
        __syncthreads();
    }

    // epilogue
#pragma unroll
    for (int mt = 0; mt < 4; ++mt) {
        int r0 = m0 + wm * 64 + mt * 16 + (lane >> 2);
#pragma unroll
        for (int nt = 0; nt < 4; ++nt) {
            int cc = n0 + wn * 32 + nt * 8 + (lane & 3) * 2;
            float bx = 0.f, by = 0.f;
            if (flags & 1) { float2 bia = *(const float2*)(bias + cc); bx = bia.x; by = bia.y; }
            float* p0 = C + (size_t)r0 * N + cc;
            float* p1 = C + (size_t)(r0 + 8) * N + cc;
            float2 v0 = make_float2(acc[mt][nt][0] + bx, acc[mt][nt][1] + by);
            float2 v1 = make_float2(acc[mt][nt][2] + bx, acc[mt][nt][3] + by);
            if (flags & 2) {
                float2 o0 = *(float2*)p0, o1 = *(float2*)p1;
                v0.x += o0.x; v0.y += o0.y; v1.x += o1.x; v1.y += o1.y;
            }
            *(float2*)p0 = v0;
            *(float2*)p1 = v1;
        }
    }
}

// ---------------- grid barrier (R5 atomic scheme) -----------------------------
__device__ __forceinline__ void gbar_arrive_wait(unsigned* cnt, unsigned target)
{
    if (threadIdx.x == 0) {
        __threadfence();
        atomicAdd(cnt, 1u);
        while (*(volatile unsigned*)cnt < target) __nanosleep(32);
        __threadfence();
    }
    __syncthreads();
}

__device__ __forceinline__ void gbar_reset(unsigned* cnt, unsigned* done, unsigned nctas)
{
    if (threadIdx.x == 0) {
        unsigned v = atomicAdd(done, 1u);
        if (v == nctas - 1u) { *done = 0u; *cnt = 0u; __threadfence(); }
    }
}

// ---------------- reservoir scans (both reservoirs, 64 CTAs each) -----------
__global__ void __launch_bounds__(256)
rscan_kernel(const float* __restrict__ pre0, const float* __restrict__ pre1,
             const float* __restrict__ W0, const float* __restrict__ W1,
             float* __restrict__ R0, float* __restrict__ R1)
{
    __shared__ __align__(16) float sW[8 * Dn];
    __shared__ __align__(16) float sR[Bn * Dn];

    int res  = blockIdx.x >> 6;
    int jblk = blockIdx.x & 63;
    int j0   = jblk * 8;
    const float* pre  = res ? pre1 : pre0;
    const float* Wres = res ? W1 : W0;
    float* Rout = res ? R1 : R0;
    unsigned* cnt = &g_cnt[res];

    int tid = threadIdx.x, lane = tid & 31, b = tid >> 5;

    for (int i = tid; i < 8 * Dn / 4; i += 256)
        ((float4*)sW)[i] = ((const float4*)(Wres + (size_t)j0 * Dn))[i];
    __syncthreads();

    for (int t = 0; t < Tn; ++t) {
        if (t == 0) {
            float4 z = make_float4(0.f, 0.f, 0.f, 0.f);
            for (int i = tid; i < Bn * Dn / 4; i += 256) ((float4*)sR)[i] = z;
        } else {
            for (int i = tid; i < Bn * Dn / 4; i += 256) {
                int bb = i >> 7, c = i & 127;
                ((float4*)sR)[i] =
                    __ldcg(((const float4*)(Rout + ((size_t)bb * Tn + (t - 1)) * Dn)) + c);
            }
        }
        __syncthreads();

        const float4* rb = (const float4*)(sR + b * Dn);
        float4 rv[4];
#pragma unroll
        for (int i = 0; i < 4; i++) rv[i] = rb[i * 32 + lane];

        float myout = 0.f;
#pragma unroll
        for (int jj = 0; jj < 8; ++jj) {
            const float4* wr = (const float4*)(sW + jj * Dn);
            float sv = 0.f;
#pragma unroll
            for (int i = 0; i < 4; i++) {
                float4 w4 = wr[i * 32 + lane];
                sv += rv[i].x * w4.x + rv[i].y * w4.y + rv[i].z * w4.z + rv[i].w * w4.w;
            }
#pragma unroll
            for (int off = 16; off; off >>= 1) sv += __shfl_xor_sync(0xffffffffu, sv, off);
            if (lane == jj) myout = sv;
        }
        if (lane < 8) {
            int j = j0 + lane;
            size_t row = (size_t)b * Tn + t;
            float rold = sR[b * Dn + j];
            float p = __ldcg(pre + row * Dn + j);
            Rout[row * Dn + j] = 0.5f * rold + 0.5f * tanhf(p + myout);
        }
        __syncthreads();
        gbar_arrive_wait(cnt, 64u * (unsigned)(t + 1));
    }
    gbar_reset(cnt, &g_done[res], 64u);
}

// ---------------- hidden scan -------------------------------------------------
__global__ void __launch_bounds__(256)
hscan_kernel(const float* __restrict__ Hpre, const float* __restrict__ Wh,
             float* __restrict__ Hout)
{
    extern __shared__ __align__(16) float smem[];
    float* sW = smem;
    float* sH = smem + 8 * Hn;

    int tid = threadIdx.x, lane = tid & 31, b = tid >> 5;
    int j0 = blockIdx.x * 8;
    unsigned* cnt = &g_cnt[2];

    for (int i = tid; i < 8 * Hn / 4; i += 256)
        ((float4*)sW)[i] = ((const float4*)(Wh + (size_t)j0 * Hn))[i];
    __syncthreads();

    for (int t = 0; t < Tn; ++t) {
        if (t == 0) {
            float4 z = make_float4(0.f, 0.f, 0.f, 0.f);
            for (int i = tid; i < Bn * Hn / 4; i += 256) ((float4*)sH)[i] = z;
        } else {
            for (int i = tid; i < Bn * Hn / 4; i += 256) {
                int bb = i >> 8, c = i & 255;
                ((float4*)sH)[i] =
                    __ldcg(((const float4*)(Hout + ((size_t)bb * Tn + (t - 1)) * Hn)) + c);
            }
        }
        __syncthreads();

        const float4* hb = (const float4*)(sH + b * Hn);
        float4 hv[8];
#pragma unroll
        for (int i = 0; i < 8; i++) hv[i] = hb[i * 32 + lane];

        float myout = 0.f;
#pragma unroll
        for (int jj = 0; jj < 8; ++jj) {
            const float4* wr = (const float4*)(sW + jj * Hn);
            float sv = 0.f;
#pragma unroll
            for (int i = 0; i < 8; i++) {
                float4 w4 = wr[i * 32 + lane];
                sv += hv[i].x * w4.x + hv[i].y * w4.y + hv[i].z * w4.z + hv[i].w * w4.w;
            }
#pragma unroll
            for (int off = 16; off; off >>= 1) sv += __shfl_xor_sync(0xffffffffu, sv, off);
            if (lane == jj) myout = sv;
        }
        if (lane < 8) {
            int j = j0 + lane;
            size_t row = (size_t)b * Tn + t;
            float p = __ldcg(Hpre + row * Hn + j);
            Hout[row * Hn + j] = tanhf(p + myout);
        }
        __syncthreads();
        gbar_arrive_wait(cnt, 128u * (unsigned)(t + 1));
    }
    gbar_reset(cnt, &g_done[2], 128u);
}

// ---------------- launch ------------------------------------------------------
extern "C" void kernel_launch(void* const* d_in, const int* in_sizes, int n_in,
                              void* d_out, int out_size)
{
    const int*   ids   = (const int*)  d_in[0];
    const float* emb   = (const float*)d_in[1];
    const float* W_x   = (const float*)d_in[2];
    const float* W_h   = (const float*)d_in[3];
    const float* b_h   = (const float*)d_in[4];
    const float* Win0  = (const float*)d_in[5];
    const float* Wres0 = (const float*)d_in[6];
    const float* U0    = (const float*)d_in[7];
    const float* Win1  = (const float*)d_in[8];
    const float* Wres1 = (const float*)d_in[9];
    const float* U1    = (const float*)d_in[10];
    const float* outW  = (const float*)d_in[11];
    const float* outb  = (const float*)d_in[12];
    float* out = (float*)d_out;

    float *R0pre, *R1pre, *R0, *R1, *Hpre, *Hst;
    __half *Xcat, *Wcat, *Win0h, *Win1h, *Wh16, *Hh16;
    cudaGetSymbolAddress((void**)&R0pre, g_R0pre);
    cudaGetSymbolAddress((void**)&R1pre, g_R1pre);
    cudaGetSymbolAddress((void**)&R0,    g_R0);
    cudaGetSymbolAddress((void**)&R1,    g_R1);
    cudaGetSymbolAddress((void**)&Hpre,  g_Hpre);
    cudaGetSymbolAddress((void**)&Hst,   g_H);
    cudaGetSymbolAddress((void**)&Xcat,  g_Xcat);
    cudaGetSymbolAddress((void**)&Wcat,  g_Wcat);
    cudaGetSymbolAddress((void**)&Win0h, g_Win0h);
    cudaGetSymbolAddress((void**)&Win1h, g_Win1h);
    cudaGetSymbolAddress((void**)&Wh16,  g_Wh);
    cudaGetSymbolAddress((void**)&Hh16,  g_Hh);

    cudaFuncSetAttribute(hscan_kernel,
                         cudaFuncAttributeMaxDynamicSharedMemorySize, 65536);
    cudaFuncSetAttribute(gemm16,
                         cudaFuncAttributeMaxDynamicSharedMemorySize, 2 * STAGEB);

    // 1) gathers + weight conversions / packs
    embed_h<<<MROWS, 256>>>(ids, emb, Xcat);
    cvt_h_kernel<<<(Dn * En / 4 + 255) / 256, 256>>>(Win0, Win0h, Dn * En / 4);
    cvt_h_kernel<<<(Dn * En / 4 + 255) / 256, 256>>>(Win1, Win1h, Dn * En / 4);
    pack_wcat<<<Hn, 512>>>(W_x, U0, U1, Wcat);
    cvt_h_kernel<<<(Vn * Hn / 4 + 255) / 256, 256>>>(outW, Wh16, Vn * Hn / 4);

    // 2) reservoir input projections (fp16 MMA, dual via z)
    gemm16<<<dim3(MROWS / 128, Dn / 128, 2), 256, 2 * STAGEB>>>(
        Xcat, Win0h, nullptr, R0pre, Win1h, R1pre, MROWS, Dn, En, KCAT, 0);

    // 3) sequential reservoir scans (fp32)
    rscan_kernel<<<128, 256>>>(R0pre, R1pre, Wres0, Wres1, R0, R1);

    // 4) R0,R1 -> fp16 into Xcat tail
    cvt_r_kernel<<<MROWS * (2 * Dn) / 4 / 256, 256>>>(R0, R1, Xcat);

    // 5) Hpre = [X|R0|R1] @ [W_x|U0|U1]^T + b_h  (one K=2048 fp16 GEMM)
    gemm16<<<dim3(MROWS / 128, Hn / 128, 1), 256, 2 * STAGEB>>>(
        Xcat, Wcat, b_h, Hpre, nullptr, nullptr, MROWS, Hn, KCAT, KCAT, 1);

    // 6) sequential hidden scan (fp32)
    hscan_kernel<<<128, 256, 65536>>>(Hpre, W_h, Hst);
    cvt_h_kernel<<<(MROWS * Hn / 4 + 255) / 256, 256>>>(Hst, Hh16, MROWS * Hn / 4);

    // 7) logits GEMM + bias (fp16 MMA)
    gemm16<<<dim3(MROWS / 128, Vn / 128, 1), 256, 2 * STAGEB>>>(
        Hh16, Wh16, outb, out, nullptr, nullptr, MROWS, Vn, Hn, Hn, 1);
}